// round 6
// baseline (speedup 1.0000x reference)
#include <cuda_runtime.h>
#include <math.h>

// Problem constants
#define T_TOK 8192
#define D_DIM 768
#define N_SPAN 10000
#define W_MAX 32

// ---------------- scratch: Y = S @ Wq^T + bq  (T x D) -------------------
__device__ float g_Y[T_TOK * D_DIM];

// ---------------- Kernel 1: fp32 SGEMM  Y[t,e] = sum_d S[t,d]*Wq[e,d] + bq[e]
// M=8192, N=768, K=768. Both operands K-major (NT GEMM).
// 128x128 block tile, BK=8, 256 threads, 8x8 micro-tile, double-buffered smem.
#define BM 128
#define BN 128
#define BK 8
#define NK_TILES (D_DIM / BK)   // 96

__global__ void __launch_bounds__(256) gemm_qproj(
    const float* __restrict__ S, const float* __restrict__ Wq,
    const float* __restrict__ bq)
{
    __shared__ float As[2][BK][BM];
    __shared__ float Bs[2][BK][BN];

    const int tid = threadIdx.x;
    const int m0 = blockIdx.y * BM;
    const int n0 = blockIdx.x * BN;
    const int tx = tid & 15;      // 0..15
    const int ty = tid >> 4;      // 0..15

    const int lrow = tid >> 1;          // 0..127
    const int lseg = (tid & 1) * 4;     // 0 or 4

    float acc[8][8];
#pragma unroll
    for (int i = 0; i < 8; i++)
#pragma unroll
        for (int j = 0; j < 8; j++) acc[i][j] = 0.f;

    const float* Ag = S  + (m0 + lrow) * D_DIM + lseg;
    const float* Bg = Wq + (n0 + lrow) * D_DIM + lseg;

    // preload tile 0
    {
        float4 a = *(const float4*)(Ag);
        float4 b = *(const float4*)(Bg);
        As[0][lseg + 0][lrow] = a.x; As[0][lseg + 1][lrow] = a.y;
        As[0][lseg + 2][lrow] = a.z; As[0][lseg + 3][lrow] = a.w;
        Bs[0][lseg + 0][lrow] = b.x; Bs[0][lseg + 1][lrow] = b.y;
        Bs[0][lseg + 2][lrow] = b.z; Bs[0][lseg + 3][lrow] = b.w;
    }
    __syncthreads();

    int buf = 0;
    for (int kt = 0; kt < NK_TILES; kt++) {
        const bool has_next = (kt + 1) < NK_TILES;
        float4 an, bn;
        if (has_next) {
            an = *(const float4*)(Ag + (kt + 1) * BK);
            bn = *(const float4*)(Bg + (kt + 1) * BK);
        }

#pragma unroll
        for (int k = 0; k < BK; k++) {
            float4 a0 = *(const float4*)&As[buf][k][ty * 4];
            float4 a1 = *(const float4*)&As[buf][k][64 + ty * 4];
            float4 b0 = *(const float4*)&Bs[buf][k][tx * 4];
            float4 b1 = *(const float4*)&Bs[buf][k][64 + tx * 4];
            float av[8] = {a0.x, a0.y, a0.z, a0.w, a1.x, a1.y, a1.z, a1.w};
            float bv[8] = {b0.x, b0.y, b0.z, b0.w, b1.x, b1.y, b1.z, b1.w};
#pragma unroll
            for (int i = 0; i < 8; i++)
#pragma unroll
                for (int j = 0; j < 8; j++)
                    acc[i][j] = fmaf(av[i], bv[j], acc[i][j]);
        }

        if (has_next) {
            const int nb = buf ^ 1;
            As[nb][lseg + 0][lrow] = an.x; As[nb][lseg + 1][lrow] = an.y;
            As[nb][lseg + 2][lrow] = an.z; As[nb][lseg + 3][lrow] = an.w;
            Bs[nb][lseg + 0][lrow] = bn.x; Bs[nb][lseg + 1][lrow] = bn.y;
            Bs[nb][lseg + 2][lrow] = bn.z; Bs[nb][lseg + 3][lrow] = bn.w;
            __syncthreads();
            buf = nb;
        }
    }

    // epilogue: add bq, store to g_Y
    float4 bq0 = *(const float4*)(bq + n0 + tx * 4);
    float4 bq1 = *(const float4*)(bq + n0 + 64 + tx * 4);
#pragma unroll
    for (int ih = 0; ih < 2; ih++) {
#pragma unroll
        for (int i0 = 0; i0 < 4; i0++) {
            int i = ih * 4 + i0;
            int m = m0 + ih * 64 + ty * 4 + i0;
            float* yp = g_Y + m * D_DIM + n0;
            float4 v0, v1;
            v0.x = acc[i][0] + bq0.x; v0.y = acc[i][1] + bq0.y;
            v0.z = acc[i][2] + bq0.z; v0.w = acc[i][3] + bq0.w;
            v1.x = acc[i][4] + bq1.x; v1.y = acc[i][5] + bq1.y;
            v1.z = acc[i][6] + bq1.z; v1.w = acc[i][7] + bq1.w;
            *(float4*)(yp + tx * 4)      = v0;
            *(float4*)(yp + 64 + tx * 4) = v1;
        }
    }
}

// ---------------- Kernel 2: per-span attention, one block per span ----------
// out[n,d] = sum_k c[k] * S[start+k, d],  c[k] = sum_q softmax_k(Y[start+q] . S[start+k])
// Row stride PAD=772 words == 4 (mod 32): for LDS.128 each 8-lane phase covers
// banks (4i+j) mod 32 exactly once -> conflict-free.
// Phase B is q-blocked (QB=4): each warp owns 4 consecutive q rows; lane = k.
// One LDS.128 s-fragment is reused across 4 y rows -> 4x less smem crossbar.
#define PAD 772
#define QB 4
#define SMEM_FLOATS (32 * PAD + 8 * 32 + 32)
#define SMEM_BYTES  (SMEM_FLOATS * 4)

__global__ void __launch_bounds__(256) span_attn(
    const float* __restrict__ S, const int* __restrict__ spans,
    float* __restrict__ out)
{
    extern __shared__ float sm[];
    float* S_sh   = sm;                 // [32][PAD]
    float* cpart  = sm + 32 * PAD;      // [8][32] per-warp partial column sums
    float* c_sh   = cpart + 8 * 32;     // [32]

    const int n = blockIdx.x;
    const int start = spans[2 * n];
    const int end   = spans[2 * n + 1];
    const int L     = end - start + 1;  // 1..32

    const int tid  = threadIdx.x;
    const int warp = tid >> 5;
    const int lane = tid & 31;

    // Phase A: load S span rows into smem (float4, row stride PAD)
    for (int i = tid; i < L * (D_DIM / 4); i += 256) {
        int r = i / (D_DIM / 4);
        int j = i - r * (D_DIM / 4);
        float4 v = *(const float4*)(S + (start + r) * D_DIM + j * 4);
        *(float4*)(S_sh + r * PAD + j * 4) = v;
    }
    __syncthreads();

    // Phase B+C: warp w handles q rows [w*QB, w*QB+QB). 8 warps x 4 = 32 slots,
    // so a single pass covers all q. Reading y rows q >= L is safe (start+q < T
    // since start < T-W and q <= 31); their results are discarded.
    float cacc = 0.f;
    const int q0 = warp * QB;
    if (q0 < L) {
        const float* Sk = S_sh + lane * PAD;
        const float4* Y0 = (const float4*)(g_Y + (start + q0) * D_DIM);
        float acc0 = 0.f, acc1 = 0.f, acc2 = 0.f, acc3 = 0.f;
#pragma unroll 4
        for (int d4 = 0; d4 < D_DIM / 4; d4++) {
            float4 s  = *(const float4*)(Sk + d4 * 4);          // LDS.128
            float4 y0 = __ldg(Y0 + d4);                         // broadcast
            float4 y1 = __ldg(Y0 + (D_DIM / 4) + d4);
            float4 y2 = __ldg(Y0 + 2 * (D_DIM / 4) + d4);
            float4 y3 = __ldg(Y0 + 3 * (D_DIM / 4) + d4);
            acc0 = fmaf(y0.x, s.x, acc0); acc0 = fmaf(y0.y, s.y, acc0);
            acc0 = fmaf(y0.z, s.z, acc0); acc0 = fmaf(y0.w, s.w, acc0);
            acc1 = fmaf(y1.x, s.x, acc1); acc1 = fmaf(y1.y, s.y, acc1);
            acc1 = fmaf(y1.z, s.z, acc1); acc1 = fmaf(y1.w, s.w, acc1);
            acc2 = fmaf(y2.x, s.x, acc2); acc2 = fmaf(y2.y, s.y, acc2);
            acc2 = fmaf(y2.z, s.z, acc2); acc2 = fmaf(y2.w, s.w, acc2);
            acc3 = fmaf(y3.x, s.x, acc3); acc3 = fmaf(y3.y, s.y, acc3);
            acc3 = fmaf(y3.z, s.z, acc3); acc3 = fmaf(y3.w, s.w, acc3);
        }
        float accs[QB] = {acc0, acc1, acc2, acc3};
#pragma unroll
        for (int j = 0; j < QB; j++) {
            if (q0 + j < L) {
                float v = (lane < L) ? accs[j] : -INFINITY;
                float m = v;
#pragma unroll
                for (int o = 16; o; o >>= 1)
                    m = fmaxf(m, __shfl_xor_sync(0xffffffffu, m, o));
                float e = __expf(v - m);           // -inf -> 0
                float s = e;
#pragma unroll
                for (int o = 16; o; o >>= 1)
                    s += __shfl_xor_sync(0xffffffffu, s, o);
                float rs = 1.0f / s;               // warp-uniform reciprocal
                cacc = fmaf(e, rs, cacc);
            }
        }
    }
    cpart[warp * 32 + lane] = cacc;
    __syncthreads();

    // c[k] = fold 8 per-warp partials
    if (warp == 0) {
        float c = cpart[lane];
#pragma unroll
        for (int w = 1; w < 8; w++) c += cpart[w * 32 + lane];
        c_sh[lane] = c;
    }
    __syncthreads();

    // Phase D: out[n] = sum_k c[k] * S_sh[k]
    for (int j = tid; j < D_DIM / 4; j += 256) {
        float4 accv = make_float4(0.f, 0.f, 0.f, 0.f);
#pragma unroll 4
        for (int k = 0; k < L; k++) {
            float ck = c_sh[k];
            float4 s = *(const float4*)(S_sh + k * PAD + j * 4);
            accv.x = fmaf(ck, s.x, accv.x);
            accv.y = fmaf(ck, s.y, accv.y);
            accv.z = fmaf(ck, s.z, accv.z);
            accv.w = fmaf(ck, s.w, accv.w);
        }
        *(float4*)(out + n * D_DIM + j * 4) = accv;
    }
}

// ---------------- launch ----------------------------------------------------
extern "C" void kernel_launch(void* const* d_in, const int* in_sizes, int n_in,
                              void* d_out, int out_size)
{
    const float* S     = (const float*)d_in[0];   // sentence_embeddings [T,D]
    const int*   spans = (const int*)  d_in[1];   // sentence_spans [N,2]
    const float* Wq    = (const float*)d_in[2];   // [D,D]
    const float* bq    = (const float*)d_in[3];   // [D]
    float* out = (float*)d_out;                   // [N,D]

    const int n_spans = in_sizes[1] / 2;

    cudaFuncSetAttribute(span_attn, cudaFuncAttributeMaxDynamicSharedMemorySize,
                         SMEM_BYTES);

    dim3 ggrid(D_DIM / BN, T_TOK / BM);
    gemm_qproj<<<ggrid, 256>>>(S, Wq, bq);
    span_attn<<<n_spans, 256, SMEM_BYTES>>>(S, spans, out);
}

// round 16
// speedup vs baseline: 1.1445x; 1.1445x over previous
#include <cuda_runtime.h>
#include <math.h>

// Problem constants
#define T_TOK 8192
#define D_DIM 768
#define N_SPAN 10000
#define W_MAX 32

// ---------------- scratch: Y = S @ Wq^T + bq  (T x D) -------------------
__device__ float g_Y[T_TOK * D_DIM];

// ---------------- Kernel 1: fp32 SGEMM  Y[t,e] = sum_d S[t,d]*Wq[e,d] + bq[e]
#define BM 128
#define BN 128
#define BK 8
#define NK_TILES (D_DIM / BK)   // 96

__global__ void __launch_bounds__(256) gemm_qproj(
    const float* __restrict__ S, const float* __restrict__ Wq,
    const float* __restrict__ bq)
{
    __shared__ float As[2][BK][BM];
    __shared__ float Bs[2][BK][BN];

    const int tid = threadIdx.x;
    const int m0 = blockIdx.y * BM;
    const int n0 = blockIdx.x * BN;
    const int tx = tid & 15;
    const int ty = tid >> 4;

    const int lrow = tid >> 1;
    const int lseg = (tid & 1) * 4;

    float acc[8][8];
#pragma unroll
    for (int i = 0; i < 8; i++)
#pragma unroll
        for (int j = 0; j < 8; j++) acc[i][j] = 0.f;

    const float* Ag = S  + (m0 + lrow) * D_DIM + lseg;
    const float* Bg = Wq + (n0 + lrow) * D_DIM + lseg;

    {
        float4 a = *(const float4*)(Ag);
        float4 b = *(const float4*)(Bg);
        As[0][lseg + 0][lrow] = a.x; As[0][lseg + 1][lrow] = a.y;
        As[0][lseg + 2][lrow] = a.z; As[0][lseg + 3][lrow] = a.w;
        Bs[0][lseg + 0][lrow] = b.x; Bs[0][lseg + 1][lrow] = b.y;
        Bs[0][lseg + 2][lrow] = b.z; Bs[0][lseg + 3][lrow] = b.w;
    }
    __syncthreads();

    int buf = 0;
    for (int kt = 0; kt < NK_TILES; kt++) {
        const bool has_next = (kt + 1) < NK_TILES;
        float4 an, bn;
        if (has_next) {
            an = *(const float4*)(Ag + (kt + 1) * BK);
            bn = *(const float4*)(Bg + (kt + 1) * BK);
        }

#pragma unroll
        for (int k = 0; k < BK; k++) {
            float4 a0 = *(const float4*)&As[buf][k][ty * 4];
            float4 a1 = *(const float4*)&As[buf][k][64 + ty * 4];
            float4 b0 = *(const float4*)&Bs[buf][k][tx * 4];
            float4 b1 = *(const float4*)&Bs[buf][k][64 + tx * 4];
            float av[8] = {a0.x, a0.y, a0.z, a0.w, a1.x, a1.y, a1.z, a1.w};
            float bv[8] = {b0.x, b0.y, b0.z, b0.w, b1.x, b1.y, b1.z, b1.w};
#pragma unroll
            for (int i = 0; i < 8; i++)
#pragma unroll
                for (int j = 0; j < 8; j++)
                    acc[i][j] = fmaf(av[i], bv[j], acc[i][j]);
        }

        if (has_next) {
            const int nb = buf ^ 1;
            As[nb][lseg + 0][lrow] = an.x; As[nb][lseg + 1][lrow] = an.y;
            As[nb][lseg + 2][lrow] = an.z; As[nb][lseg + 3][lrow] = an.w;
            Bs[nb][lseg + 0][lrow] = bn.x; Bs[nb][lseg + 1][lrow] = bn.y;
            Bs[nb][lseg + 2][lrow] = bn.z; Bs[nb][lseg + 3][lrow] = bn.w;
            __syncthreads();
            buf = nb;
        }
    }

    float4 bq0 = *(const float4*)(bq + n0 + tx * 4);
    float4 bq1 = *(const float4*)(bq + n0 + 64 + tx * 4);
#pragma unroll
    for (int ih = 0; ih < 2; ih++) {
#pragma unroll
        for (int i0 = 0; i0 < 4; i0++) {
            int i = ih * 4 + i0;
            int m = m0 + ih * 64 + ty * 4 + i0;
            float* yp = g_Y + m * D_DIM + n0;
            float4 v0, v1;
            v0.x = acc[i][0] + bq0.x; v0.y = acc[i][1] + bq0.y;
            v0.z = acc[i][2] + bq0.z; v0.w = acc[i][3] + bq0.w;
            v1.x = acc[i][4] + bq1.x; v1.y = acc[i][5] + bq1.y;
            v1.z = acc[i][6] + bq1.z; v1.w = acc[i][7] + bq1.w;
            *(float4*)(yp + tx * 4)      = v0;
            *(float4*)(yp + 64 + tx * 4) = v1;
        }
    }
}

// ---------------- Kernel 2: per-span attention, one block per span ----------
// Phase B is q-blocked (QB=4) and 3-stage software-pipelined so ~15 loads are
// in flight per warp (load->use distance ~2 iterations) to cover L2 latency.
// The first 12 y LDGs are issued BEFORE the Phase-A barrier (they touch only
// g_Y, never smem) so one L2 round-trip overlaps the smem staging.
#define PAD 772
#define QB 4
#define ND4 (D_DIM / 4)   // 192, divisible by 3
#define SMEM_FLOATS (32 * PAD + 8 * 32 + 32)
#define SMEM_BYTES  (SMEM_FLOATS * 4)

#define LOAD_Y(st, d4)                                              \
    y##st##0 = __ldg(Yr0 + (d4));                                   \
    y##st##1 = __ldg(Yr1 + (d4));                                   \
    y##st##2 = __ldg(Yr2 + (d4));                                   \
    y##st##3 = __ldg(Yr3 + (d4));

#define LOAD_S(st, d4)                                              \
    s##st = *(const float4*)(Sk + (d4) * 4);

#define LOADSTAGE(st, d4)  LOAD_S(st, d4) LOAD_Y(st, d4)

// Two-level macro: token-pasting happens on bare identifiers (yC0 etc.);
// member access happens on the FMA4 parameter, avoiding the "3.x" pp-number
// pasting bug that broke the previous build.
#define FMA4(acc, yv, sv)                                           \
    acc = fmaf((yv).x, (sv).x, acc);                                \
    acc = fmaf((yv).y, (sv).y, acc);                                \
    acc = fmaf((yv).z, (sv).z, acc);                                \
    acc = fmaf((yv).w, (sv).w, acc);

#define FMASTAGE(st)                                                \
    FMA4(a0, y##st##0, s##st)                                       \
    FMA4(a1, y##st##1, s##st)                                       \
    FMA4(a2, y##st##2, s##st)                                       \
    FMA4(a3, y##st##3, s##st)

__global__ void __launch_bounds__(256, 2) span_attn(
    const float* __restrict__ S, const int* __restrict__ spans,
    float* __restrict__ out)
{
    extern __shared__ float sm[];
    float* S_sh   = sm;                 // [32][PAD]
    float* cpart  = sm + 32 * PAD;      // [8][32]
    float* c_sh   = cpart + 8 * 32;     // [32]

    const int n = blockIdx.x;
    const int start = spans[2 * n];
    const int end   = spans[2 * n + 1];
    const int L     = end - start + 1;  // 1..32

    const int tid  = threadIdx.x;
    const int warp = tid >> 5;
    const int lane = tid & 31;

    const int q0 = warp * QB;
    const bool active = (q0 < L);

    // Pipeline state (y rows live in g_Y only: q rows >= L are safe to read
    // since start < T-W implies start+q < T; their results are discarded).
    const float*  Sk  = S_sh + lane * PAD;
    const float4* Yr0 = (const float4*)(g_Y + (start + q0) * D_DIM);
    const float4* Yr1 = Yr0 + ND4;
    const float4* Yr2 = Yr0 + 2 * ND4;
    const float4* Yr3 = Yr0 + 3 * ND4;

    float4 sA, yA0, yA1, yA2, yA3;
    float4 sB, yB0, yB1, yB2, yB3;
    float4 sC, yC0, yC1, yC2, yC3;

    // Prime y loads BEFORE the barrier — they never touch smem.
    if (active) {
        LOAD_Y(A, 0)
        LOAD_Y(B, 1)
        LOAD_Y(C, 2)
    }

    // Phase A: stage S span rows (row stride PAD=772: conflict-free, audited)
    for (int i = tid; i < L * ND4; i += 256) {
        int r = i / ND4;
        int j = i - r * ND4;
        float4 v = *(const float4*)(S + (start + r) * D_DIM + j * 4);
        *(float4*)(S_sh + r * PAD + j * 4) = v;
    }
    __syncthreads();

    // Phase B+C: warp w owns q rows [w*4, w*4+4); lane = k.
    float cacc = 0.f;
    if (active) {
        float a0 = 0.f, a1 = 0.f, a2 = 0.f, a3 = 0.f;
        LOAD_S(A, 0)
        LOAD_S(B, 1)
        LOAD_S(C, 2)

        for (int d4 = 0; d4 < ND4; d4 += 3) {
            FMASTAGE(A)
            if (d4 + 3 < ND4) { LOADSTAGE(A, d4 + 3) }
            FMASTAGE(B)
            if (d4 + 4 < ND4) { LOADSTAGE(B, d4 + 4) }
            FMASTAGE(C)
            if (d4 + 5 < ND4) { LOADSTAGE(C, d4 + 5) }
        }

        float accs[QB] = {a0, a1, a2, a3};
#pragma unroll
        for (int j = 0; j < QB; j++) {
            if (q0 + j < L) {
                float v = (lane < L) ? accs[j] : -INFINITY;
                float m = v;
#pragma unroll
                for (int o = 16; o; o >>= 1)
                    m = fmaxf(m, __shfl_xor_sync(0xffffffffu, m, o));
                float e = __expf(v - m);           // -inf -> 0
                float s = e;
#pragma unroll
                for (int o = 16; o; o >>= 1)
                    s += __shfl_xor_sync(0xffffffffu, s, o);
                float rs = 1.0f / s;               // warp-uniform
                cacc = fmaf(e, rs, cacc);
            }
        }
    }
    cpart[warp * 32 + lane] = cacc;
    __syncthreads();

    if (warp == 0) {
        float c = cpart[lane];
#pragma unroll
        for (int w = 1; w < 8; w++) c += cpart[w * 32 + lane];
        c_sh[lane] = c;
    }
    __syncthreads();

    // Phase D: out[n] = sum_k c[k] * S_sh[k]
    for (int j = tid; j < ND4; j += 256) {
        float4 accv = make_float4(0.f, 0.f, 0.f, 0.f);
#pragma unroll 8
        for (int k = 0; k < L; k++) {
            float ck = c_sh[k];
            float4 s = *(const float4*)(S_sh + k * PAD + j * 4);
            accv.x = fmaf(ck, s.x, accv.x);
            accv.y = fmaf(ck, s.y, accv.y);
            accv.z = fmaf(ck, s.z, accv.z);
            accv.w = fmaf(ck, s.w, accv.w);
        }
        *(float4*)(out + n * D_DIM + j * 4) = accv;
    }
}

// ---------------- launch ----------------------------------------------------
extern "C" void kernel_launch(void* const* d_in, const int* in_sizes, int n_in,
                              void* d_out, int out_size)
{
    const float* S     = (const float*)d_in[0];   // [T,D]
    const int*   spans = (const int*)  d_in[1];   // [N,2]
    const float* Wq    = (const float*)d_in[2];   // [D,D]
    const float* bq    = (const float*)d_in[3];   // [D]
    float* out = (float*)d_out;                   // [N,D]

    const int n_spans = in_sizes[1] / 2;

    cudaFuncSetAttribute(span_attn, cudaFuncAttributeMaxDynamicSharedMemorySize,
                         SMEM_BYTES);

    dim3 ggrid(D_DIM / BN, T_TOK / BM);
    gemm_qproj<<<ggrid, 256>>>(S, Wq, bq);
    span_attn<<<n_spans, 256, SMEM_BYTES>>>(S, spans, out);
}